// round 9
// baseline (speedup 1.0000x reference)
#include <cuda_runtime.h>
#include <cuda_fp16.h>
#include <stdint.h>

// Problem constants
#define BB 16
#define NN 8192
#define DD 256
#define HH 128
#define NP 64
#define KSEL 32
#define ROWS (BB * NN)          // 131072
#define SEL_PER_B (NP * KSEL)   // 2048

#define LO_SCALE 2048.0f        // 2^11
#define LO_INV   (1.0f / 2048.0f)

// ---- fp16 pack helpers ----
__device__ __forceinline__ uint32_t pack_h2(float x, float y) {
    __half2 h = __floats2half2_rn(x, y);
    return *reinterpret_cast<uint32_t*>(&h);
}
__device__ __forceinline__ float2 unpack_h2(uint32_t u) {
    __half2 h = *reinterpret_cast<__half2*>(&u);
    return __half22float2(h);
}

__device__ __forceinline__ void mma_f16(float c[4],
                                        uint32_t a0, uint32_t a1, uint32_t a2, uint32_t a3,
                                        uint32_t b0, uint32_t b1) {
    asm volatile(
        "mma.sync.aligned.m16n8k16.row.col.f32.f16.f16.f32 "
        "{%0,%1,%2,%3}, {%4,%5,%6,%7}, {%8,%9}, {%0,%1,%2,%3};"
        : "+f"(c[0]), "+f"(c[1]), "+f"(c[2]), "+f"(c[3])
        : "r"(a0), "r"(a1), "r"(a2), "r"(a3), "r"(b0), "r"(b1));
}

__device__ __forceinline__ uint32_t smem_u32(const void* p) {
    uint32_t a;
    asm("{ .reg .u64 t; cvta.to.shared.u64 t, %1; cvt.u32.u64 %0, t; }" : "=r"(a) : "l"(p));
    return a;
}
__device__ __forceinline__ void cp_async16(uint32_t dst, const void* src) {
    asm volatile("cp.async.cg.shared.global [%0], [%1], 16;" :: "r"(dst), "l"(src));
}
__device__ __forceinline__ void cp_async8(uint32_t dst, const void* src) {
    asm volatile("cp.async.ca.shared.global [%0], [%1], 8;" :: "r"(dst), "l"(src));
}
#define CP_COMMIT() asm volatile("cp.async.commit_group;")
#define CP_WAIT0()  asm volatile("cp.async.wait_group 0;")

// W1 planes in mma B-fragment layout: plane 0 = fp16(w), plane 1 = fp16((w - hi) * 2^11)
// g_Bf[kt][nt][plane][lane] = uint2 {b0, b1}
__device__ uint2 g_Bf[16][16][2][32];

// ============================================================
// K0: build split W1 fragment table (fp16 hi + scaled lo)
// ============================================================
__global__ void k_prepB(const float* __restrict__ W1)
{
    int idx  = blockIdx.x * 256 + threadIdx.x;   // 0..16383
    int lane = idx & 31;
    int pl   = (idx >> 5) & 1;
    int nt   = (idx >> 6) & 15;
    int kt   = idx >> 10;

    int k0 = kt * 16 + (lane & 3) * 2;
    int n  = nt * 8 + (lane >> 2);

    uint32_t reg[2];
#pragma unroll
    for (int r = 0; r < 2; r++) {
        int k = k0 + r * 8;
        float v0 = W1[(size_t)k * HH + n];
        float v1 = W1[(size_t)(k + 1) * HH + n];
        uint32_t h = pack_h2(v0, v1);
        if (pl == 0) {
            reg[r] = h;
        } else {
            float2 f = unpack_h2(h);
            reg[r] = pack_h2((v0 - f.x) * LO_SCALE, (v1 - f.y) * LO_SCALE);
        }
    }
    g_Bf[kt][nt][pl][lane] = make_uint2(reg[0], reg[1]);
}

// ============================================================
// K1: logits = relu(features @ W1 + b1) @ W2 + b2
// fp16 2-plane split, 3 products: hi*hi -> acc1; hi*lo + lo*hi
// (both scaled 2^11) -> acc2. hidden = acc1 + acc2/2^11.
// CTA: 128x128, 256 threads, 8 warps (2 wm x 4 wn), warp 64x32.
// A and B double-buffered in smem via cp.async.
// ============================================================
#define ASTRIDE 18   // floats per A smem row

__global__ __launch_bounds__(256, 1)
void k_logits_tc(const float* __restrict__ features,
                 const float* __restrict__ b1,
                 const float* __restrict__ W2,
                 const float* __restrict__ b2,
                 float* __restrict__ logits)
{
    __shared__ float sA[2][128][ASTRIDE];
    __shared__ uint2 sB[2][16][2][32];
    __shared__ float s_b1[HH], s_w2[HH];
    __shared__ float s_red[128][4];

    const int tid  = threadIdx.x;
    const int wid  = tid >> 5;
    const int lane = tid & 31;
    const int wm   = wid >> 2;       // 0..1 (row half)
    const int wn   = wid & 3;        // 0..3 (col quarter)
    const int g    = lane >> 2;      // 0..7
    const int tig  = lane & 3;       // 0..3
    const int row0 = blockIdx.x * 128;

    if (tid < HH) { s_b1[tid] = b1[tid]; s_w2[tid] = W2[tid]; }

    const float* Abase = features + (size_t)row0 * DD;

    auto prefetch = [&](int stage, int kt) {
        const int koff = kt * 16;
#pragma unroll
        for (int i = 0; i < 4; i++) {
            int cidx = tid + 256 * i;       // 0..1023 (8B chunks)
            int r = cidx >> 3;
            int c = cidx & 7;
            cp_async8(smem_u32(&sA[stage][r][c * 2]),
                      Abase + (size_t)r * DD + koff + c * 2);
        }
        const char* src = (const char*)&g_Bf[kt][0][0][0];
        uint32_t dst = smem_u32(&sB[stage][0][0][0]);
#pragma unroll
        for (int i = 0; i < 2; i++) {
            int c = tid + 256 * i;          // 0..511 (16B chunks)
            cp_async16(dst + c * 16, src + c * 16);
        }
        CP_COMMIT();
    };

    prefetch(0, 0);

    float acc1[4][4][4], acc2[4][4][4];
#pragma unroll
    for (int mt = 0; mt < 4; mt++)
#pragma unroll
        for (int nt = 0; nt < 4; nt++)
#pragma unroll
            for (int c = 0; c < 4; c++) { acc1[mt][nt][c] = 0.0f; acc2[mt][nt][c] = 0.0f; }

    const int rg = wm * 64 + g;
    const int kcol = tig * 2;

    for (int kt = 0; kt < 16; kt++) {
        const int buf = kt & 1;
        CP_WAIT0();
        __syncthreads();
        if (kt < 15) prefetch(buf ^ 1, kt + 1);

        // B fragments for this warp's 4 nt tiles (both planes)
        uint2 bh[4], bl[4];
#pragma unroll
        for (int nt = 0; nt < 4; nt++) {
            const int ntg = wn * 4 + nt;
            bh[nt] = sB[buf][ntg][0][lane];
            bl[nt] = sB[buf][ntg][1][lane];
        }

        // A fragments: hi + scaled lo
        uint32_t Ah[4][4], Al[4][4];
#pragma unroll
        for (int mt = 0; mt < 4; mt++) {
            const int r0 = rg + mt * 16;
            float2 v00 = *(const float2*)&sA[buf][r0][kcol];
            float2 v10 = *(const float2*)&sA[buf][r0 + 8][kcol];
            float2 v01 = *(const float2*)&sA[buf][r0][kcol + 8];
            float2 v11 = *(const float2*)&sA[buf][r0 + 8][kcol + 8];
            Ah[mt][0] = pack_h2(v00.x, v00.y);
            Ah[mt][1] = pack_h2(v10.x, v10.y);
            Ah[mt][2] = pack_h2(v01.x, v01.y);
            Ah[mt][3] = pack_h2(v11.x, v11.y);
            float2 f;
            f = unpack_h2(Ah[mt][0]); Al[mt][0] = pack_h2((v00.x - f.x) * LO_SCALE, (v00.y - f.y) * LO_SCALE);
            f = unpack_h2(Ah[mt][1]); Al[mt][1] = pack_h2((v10.x - f.x) * LO_SCALE, (v10.y - f.y) * LO_SCALE);
            f = unpack_h2(Ah[mt][2]); Al[mt][2] = pack_h2((v01.x - f.x) * LO_SCALE, (v01.y - f.y) * LO_SCALE);
            f = unpack_h2(Ah[mt][3]); Al[mt][3] = pack_h2((v11.x - f.x) * LO_SCALE, (v11.y - f.y) * LO_SCALE);
        }

        // 3 product passes, each 16 independent MMAs
#pragma unroll
        for (int nt = 0; nt < 4; nt++)
#pragma unroll
            for (int mt = 0; mt < 4; mt++)
                mma_f16(acc1[mt][nt], Ah[mt][0], Ah[mt][1], Ah[mt][2], Ah[mt][3], bh[nt].x, bh[nt].y);
#pragma unroll
        for (int nt = 0; nt < 4; nt++)
#pragma unroll
            for (int mt = 0; mt < 4; mt++)
                mma_f16(acc2[mt][nt], Ah[mt][0], Ah[mt][1], Ah[mt][2], Ah[mt][3], bl[nt].x, bl[nt].y);
#pragma unroll
        for (int nt = 0; nt < 4; nt++)
#pragma unroll
            for (int mt = 0; mt < 4; mt++)
                mma_f16(acc2[mt][nt], Al[mt][0], Al[mt][1], Al[mt][2], Al[mt][3], bh[nt].x, bh[nt].y);
    }

    // Epilogue: hidden = acc1 + acc2/2^11; relu(hidden + b1) * W2; reduce
    float rs[8];
#pragma unroll
    for (int i = 0; i < 8; i++) rs[i] = 0.0f;
#pragma unroll
    for (int nt = 0; nt < 4; nt++) {
        const int c = wn * 32 + nt * 8 + tig * 2;
        float bb0 = s_b1[c],     w0 = s_w2[c];
        float bb1 = s_b1[c + 1], w1 = s_w2[c + 1];
#pragma unroll
        for (int mt = 0; mt < 4; mt++) {
            float x0 = acc1[mt][nt][0] + acc2[mt][nt][0] * LO_INV + bb0; x0 = x0 > 0.0f ? x0 : 0.0f;
            float x1 = acc1[mt][nt][1] + acc2[mt][nt][1] * LO_INV + bb1; x1 = x1 > 0.0f ? x1 : 0.0f;
            float x2 = acc1[mt][nt][2] + acc2[mt][nt][2] * LO_INV + bb0; x2 = x2 > 0.0f ? x2 : 0.0f;
            float x3 = acc1[mt][nt][3] + acc2[mt][nt][3] * LO_INV + bb1; x3 = x3 > 0.0f ? x3 : 0.0f;
            rs[2 * mt + 0] += x0 * w0 + x1 * w1;
            rs[2 * mt + 1] += x2 * w0 + x3 * w1;
        }
    }
#pragma unroll
    for (int off = 1; off <= 2; off <<= 1)
#pragma unroll
        for (int i = 0; i < 8; i++)
            rs[i] += __shfl_xor_sync(0xFFFFFFFFu, rs[i], off);

    if (tig == 0) {
#pragma unroll
        for (int mt = 0; mt < 4; mt++) {
            s_red[rg + mt * 16][wn]     = rs[2 * mt + 0];
            s_red[rg + mt * 16 + 8][wn] = rs[2 * mt + 1];
        }
    }
    __syncthreads();
    if (tid < 128)
        logits[(size_t)row0 + tid] = s_red[tid][0] + s_red[tid][1]
                                   + s_red[tid][2] + s_red[tid][3] + __ldg(b2);
}

// ============================================================
// K2: per (batch, parcel) top-32 of z = logits + gumbel.
// ============================================================
__global__ void k_select(const float* __restrict__ logits,
                         const float* __restrict__ gumbel,
                         float* __restrict__ out_idx)
{
    const int g = blockIdx.x * (blockDim.x >> 5) + (threadIdx.x >> 5);
    const int lane = threadIdx.x & 31;
    const int b = g >> 6;
    const int p = g & 63;
    const float NEG_INF = __int_as_float(0xff800000);

    float v[4];
    int nidx[4];
#pragma unroll
    for (int q = 0; q < 4; q++) {
        int n = p + 64 * (lane + 32 * q);
        size_t off = (size_t)b * NN + n;
        v[q] = logits[off] + gumbel[off];
        nidx[q] = n;
    }

    for (int it = 0; it < KSEL; it++) {
        float bv = v[0]; int bn = nidx[0];
#pragma unroll
        for (int q = 1; q < 4; q++)
            if (v[q] > bv || (v[q] == bv && nidx[q] < bn)) { bv = v[q]; bn = nidx[q]; }
#pragma unroll
        for (int off = 16; off; off >>= 1) {
            float ov = __shfl_xor_sync(0xFFFFFFFFu, bv, off);
            int   on = __shfl_xor_sync(0xFFFFFFFFu, bn, off);
            if (ov > bv || (ov == bv && on < bn)) { bv = ov; bn = on; }
        }
        if (lane == 0)
            out_idx[(size_t)b * SEL_PER_B + p * KSEL + it] = (float)bn;
#pragma unroll
        for (int q = 0; q < 4; q++)
            if (nidx[q] == bn) v[q] = NEG_INF;
    }
}

// ============================================================
// K3: gather selected patch rows (warp per row).
// ============================================================
__global__ __launch_bounds__(256)
void k_gather(const float* __restrict__ patches,
              const float* __restrict__ out_idx,
              float* __restrict__ out_sel)
{
    const int gw = blockIdx.x * 8 + (threadIdx.x >> 5);
    const int lane = threadIdx.x & 31;
    const int b = gw >> 11;
    const int j = gw & 2047;
    const int n = (int)out_idx[(size_t)b * SEL_PER_B + j];
    const float4* src = (const float4*)&patches[((size_t)b * NN + n) * DD];
    float4* dst = (float4*)&out_sel[((size_t)b * SEL_PER_B + j) * DD];
    dst[lane]      = src[lane];
    dst[lane + 32] = src[lane + 32];
}

// ============================================================
// launch
// ============================================================
extern "C" void kernel_launch(void* const* d_in, const int* in_sizes, int n_in,
                              void* d_out, int out_size)
{
    const float* patches  = (const float*)d_in[0];
    const float* features = (const float*)d_in[1];
    const float* W1       = (const float*)d_in[2];
    const float* b1       = (const float*)d_in[3];
    const float* W2       = (const float*)d_in[4];
    const float* b2       = (const float*)d_in[5];
    const float* gumbel   = (const float*)d_in[6];

    float* out      = (float*)d_out;
    float* out_sel  = out;                                 // [B, 2048, 256]
    float* out_idx  = out + (size_t)BB * SEL_PER_B * DD;   // [B, 2048]
    float* out_log  = out_idx + (size_t)BB * SEL_PER_B;    // [B, N]

    k_prepB<<<64, 256>>>(W1);
    k_logits_tc<<<ROWS / 128, 256>>>(features, b1, W2, b2, out_log);
    k_select<<<(BB * NP) / 8, 256>>>(out_log, gumbel, out_idx);
    k_gather<<<BB * SEL_PER_B / 8, 256>>>(patches, out_idx, out_sel);
}

// round 10
// speedup vs baseline: 1.3128x; 1.3128x over previous
#include <cuda_runtime.h>
#include <cuda_fp16.h>
#include <stdint.h>

// Problem constants
#define BB 16
#define NN 8192
#define DD 256
#define HH 128
#define NP 64
#define KSEL 32
#define ROWS (BB * NN)          // 131072
#define SEL_PER_B (NP * KSEL)   // 2048

#define LO_SCALE 2048.0f        // 2^11 (applied to B residual plane only)
#define LO_INV   (1.0f / 2048.0f)

// ---- fp16 pack helpers ----
__device__ __forceinline__ uint32_t pack_h2(float x, float y) {
    __half2 h = __floats2half2_rn(x, y);
    return *reinterpret_cast<uint32_t*>(&h);
}
__device__ __forceinline__ float2 unpack_h2(uint32_t u) {
    __half2 h = *reinterpret_cast<__half2*>(&u);
    return __half22float2(h);
}

// mma with accumulate into c (d == c)
__device__ __forceinline__ void mma_f16(float c[4],
                                        uint32_t a0, uint32_t a1, uint32_t a2, uint32_t a3,
                                        uint32_t b0, uint32_t b1) {
    asm volatile(
        "mma.sync.aligned.m16n8k16.row.col.f32.f16.f16.f32 "
        "{%0,%1,%2,%3}, {%4,%5,%6,%7}, {%8,%9}, {%0,%1,%2,%3};"
        : "+f"(c[0]), "+f"(c[1]), "+f"(c[2]), "+f"(c[3])
        : "r"(a0), "r"(a1), "r"(a2), "r"(a3), "r"(b0), "r"(b1));
}
// mma with explicit zero C (fresh product): d = a*b + z
__device__ __forceinline__ void mma_f16_z(float d[4],
                                          uint32_t a0, uint32_t a1, uint32_t a2, uint32_t a3,
                                          uint32_t b0, uint32_t b1,
                                          const float z[4]) {
    asm volatile(
        "mma.sync.aligned.m16n8k16.row.col.f32.f16.f16.f32 "
        "{%0,%1,%2,%3}, {%4,%5,%6,%7}, {%8,%9}, {%10,%11,%12,%13};"
        : "=f"(d[0]), "=f"(d[1]), "=f"(d[2]), "=f"(d[3])
        : "r"(a0), "r"(a1), "r"(a2), "r"(a3), "r"(b0), "r"(b1),
          "f"(z[0]), "f"(z[1]), "f"(z[2]), "f"(z[3]));
}

__device__ __forceinline__ uint32_t smem_u32(const void* p) {
    uint32_t a;
    asm("{ .reg .u64 t; cvta.to.shared.u64 t, %1; cvt.u32.u64 %0, t; }" : "=r"(a) : "l"(p));
    return a;
}
__device__ __forceinline__ void cp_async16(uint32_t dst, const void* src) {
    asm volatile("cp.async.cg.shared.global [%0], [%1], 16;" :: "r"(dst), "l"(src));
}
__device__ __forceinline__ void cp_async8(uint32_t dst, const void* src) {
    asm volatile("cp.async.ca.shared.global [%0], [%1], 8;" :: "r"(dst), "l"(src));
}
#define CP_COMMIT() asm volatile("cp.async.commit_group;")
#define CP_WAIT0()  asm volatile("cp.async.wait_group 0;")

// W1 planes, mma B-fragment layout:
// plane 0 = fp16(w), plane 1 = fp16((w - hi) * 2^11)
__device__ uint2 g_Bf[16][16][2][32];

// ============================================================
// K0: build W1 fragment table (fp16 hi + scaled lo)
// ============================================================
__global__ void k_prepB(const float* __restrict__ W1)
{
    int idx  = blockIdx.x * 256 + threadIdx.x;   // 0..16383
    int lane = idx & 31;
    int pl   = (idx >> 5) & 1;
    int nt   = (idx >> 6) & 15;
    int kt   = idx >> 10;

    int k0 = kt * 16 + (lane & 3) * 2;
    int n  = nt * 8 + (lane >> 2);

    uint32_t reg[2];
#pragma unroll
    for (int r = 0; r < 2; r++) {
        int k = k0 + r * 8;
        float v0 = W1[(size_t)k * HH + n];
        float v1 = W1[(size_t)(k + 1) * HH + n];
        uint32_t h = pack_h2(v0, v1);
        if (pl == 0) {
            reg[r] = h;
        } else {
            float2 f = unpack_h2(h);
            reg[r] = pack_h2((v0 - f.x) * LO_SCALE, (v1 - f.y) * LO_SCALE);
        }
    }
    g_Bf[kt][nt][pl][lane] = make_uint2(reg[0], reg[1]);
}

// ============================================================
// K1: logits = relu(features @ W1 + b1) @ W2 + b2
// fp16 3-product split in the round-8 shape:
//   acc += Ah*Bh;  acc += Al*Bh;  tmp = Ah*Bl(scaled 2^11), acc += tmp/2^11
// CTA 128x128, 128 threads, 4 warps (2wm x 2wn), warp 64x64, 2 CTAs/SM.
// A and B double-buffered in smem via cp.async.
// ============================================================
#define ASTRIDE 18

__global__ __launch_bounds__(128, 2)
void k_logits_tc(const float* __restrict__ features,
                 const float* __restrict__ b1,
                 const float* __restrict__ W2,
                 const float* __restrict__ b2,
                 float* __restrict__ logits)
{
    __shared__ float sA[2][128][ASTRIDE];
    __shared__ uint2 sB[2][16][2][32];
    __shared__ float s_b1[HH], s_w2[HH];
    __shared__ float s_red[128][2];

    const int tid  = threadIdx.x;
    const int wid  = tid >> 5;
    const int lane = tid & 31;
    const int wm   = wid >> 1;
    const int wn   = wid & 1;
    const int g    = lane >> 2;
    const int tig  = lane & 3;
    const int row0 = blockIdx.x * 128;

    if (tid < HH) { s_b1[tid] = b1[tid]; s_w2[tid] = W2[tid]; }

    const float* Abase = features + (size_t)row0 * DD;

    auto prefetch = [&](int stage, int kt) {
        const int koff = kt * 16;
#pragma unroll
        for (int i = 0; i < 8; i++) {
            int cidx = tid + 128 * i;
            int r = cidx >> 3;
            int c = cidx & 7;
            cp_async8(smem_u32(&sA[stage][r][c * 2]),
                      Abase + (size_t)r * DD + koff + c * 2);
        }
        const char* src = (const char*)&g_Bf[kt][0][0][0];
        uint32_t dst = smem_u32(&sB[stage][0][0][0]);
#pragma unroll
        for (int i = 0; i < 4; i++) {
            int c = tid + 128 * i;
            cp_async16(dst + c * 16, src + c * 16);
        }
        CP_COMMIT();
    };

    prefetch(0, 0);

    float acc[4][8][4];
#pragma unroll
    for (int mt = 0; mt < 4; mt++)
#pragma unroll
        for (int nt = 0; nt < 8; nt++)
#pragma unroll
            for (int c = 0; c < 4; c++) acc[mt][nt][c] = 0.0f;

    float zc[4] = {0.0f, 0.0f, 0.0f, 0.0f};   // pinned zero C operand

    const int rg = wm * 64 + g;
    const int kcol = tig * 2;

    for (int kt = 0; kt < 16; kt++) {
        const int buf = kt & 1;
        CP_WAIT0();
        __syncthreads();
        if (kt < 15) prefetch(buf ^ 1, kt + 1);

        // B fragments (both planes) for this warp's 8 nt tiles
        uint2 bh[8], bl[8];
#pragma unroll
        for (int nt = 0; nt < 8; nt++) {
            const int ntg = wn * 8 + nt;
            bh[nt] = sB[buf][ntg][0][lane];
            bl[nt] = sB[buf][ntg][1][lane];
        }

        // A fragments: fp16 hi + unscaled fp16 residual
        uint32_t Ah[4][4], Al[4][4];
#pragma unroll
        for (int mt = 0; mt < 4; mt++) {
            const int r0 = rg + mt * 16;
            float2 v00 = *(const float2*)&sA[buf][r0][kcol];
            float2 v10 = *(const float2*)&sA[buf][r0 + 8][kcol];
            float2 v01 = *(const float2*)&sA[buf][r0][kcol + 8];
            float2 v11 = *(const float2*)&sA[buf][r0 + 8][kcol + 8];
            Ah[mt][0] = pack_h2(v00.x, v00.y);
            Ah[mt][1] = pack_h2(v10.x, v10.y);
            Ah[mt][2] = pack_h2(v01.x, v01.y);
            Ah[mt][3] = pack_h2(v11.x, v11.y);
            float2 f;
            f = unpack_h2(Ah[mt][0]); Al[mt][0] = pack_h2(v00.x - f.x, v00.y - f.y);
            f = unpack_h2(Ah[mt][1]); Al[mt][1] = pack_h2(v10.x - f.x, v10.y - f.y);
            f = unpack_h2(Ah[mt][2]); Al[mt][2] = pack_h2(v01.x - f.x, v01.y - f.y);
            f = unpack_h2(Ah[mt][3]); Al[mt][3] = pack_h2(v11.x - f.x, v11.y - f.y);
        }

        // pass 1: hi*hi -> acc (32 independent MMAs)
#pragma unroll
        for (int nt = 0; nt < 8; nt++)
#pragma unroll
            for (int mt = 0; mt < 4; mt++)
                mma_f16(acc[mt][nt], Ah[mt][0], Ah[mt][1], Ah[mt][2], Ah[mt][3], bh[nt].x, bh[nt].y);
        // pass 2: lo*hi -> acc (same scale, 32 MMAs)
#pragma unroll
        for (int nt = 0; nt < 8; nt++)
#pragma unroll
            for (int mt = 0; mt < 4; mt++)
                mma_f16(acc[mt][nt], Al[mt][0], Al[mt][1], Al[mt][2], Al[mt][3], bh[nt].x, bh[nt].y);
        // pass 3: hi*lo (scaled 2^11) -> tmp, fold acc += tmp/2^11
#pragma unroll
        for (int nt = 0; nt < 8; nt++)
#pragma unroll
            for (int mt = 0; mt < 4; mt++) {
                float tmp[4];
                mma_f16_z(tmp, Ah[mt][0], Ah[mt][1], Ah[mt][2], Ah[mt][3],
                          bl[nt].x, bl[nt].y, zc);
#pragma unroll
                for (int c = 0; c < 4; c++)
                    acc[mt][nt][c] = fmaf(tmp[c], LO_INV, acc[mt][nt][c]);
            }
    }

    // Epilogue: relu(acc + b1) * W2, reduce over hidden
    float rs[8];
#pragma unroll
    for (int i = 0; i < 8; i++) rs[i] = 0.0f;
#pragma unroll
    for (int nt = 0; nt < 8; nt++) {
        const int c = wn * 64 + nt * 8 + tig * 2;
        float bb0 = s_b1[c],     w0 = s_w2[c];
        float bb1 = s_b1[c + 1], w1 = s_w2[c + 1];
#pragma unroll
        for (int mt = 0; mt < 4; mt++) {
            float x0 = acc[mt][nt][0] + bb0; x0 = x0 > 0.0f ? x0 : 0.0f;
            float x1 = acc[mt][nt][1] + bb1; x1 = x1 > 0.0f ? x1 : 0.0f;
            float x2 = acc[mt][nt][2] + bb0; x2 = x2 > 0.0f ? x2 : 0.0f;
            float x3 = acc[mt][nt][3] + bb1; x3 = x3 > 0.0f ? x3 : 0.0f;
            rs[2 * mt + 0] += x0 * w0 + x1 * w1;
            rs[2 * mt + 1] += x2 * w0 + x3 * w1;
        }
    }
#pragma unroll
    for (int off = 1; off <= 2; off <<= 1)
#pragma unroll
        for (int i = 0; i < 8; i++)
            rs[i] += __shfl_xor_sync(0xFFFFFFFFu, rs[i], off);

    if (tig == 0) {
#pragma unroll
        for (int mt = 0; mt < 4; mt++) {
            s_red[wm * 64 + mt * 16 + g][wn]     = rs[2 * mt + 0];
            s_red[wm * 64 + mt * 16 + g + 8][wn] = rs[2 * mt + 1];
        }
    }
    __syncthreads();
    if (tid < 128)
        logits[(size_t)row0 + tid] = s_red[tid][0] + s_red[tid][1] + __ldg(b2);
}

// ============================================================
// K2: per (batch, parcel) top-32 of z = logits + gumbel.
// ============================================================
__global__ void k_select(const float* __restrict__ logits,
                         const float* __restrict__ gumbel,
                         float* __restrict__ out_idx)
{
    const int g = blockIdx.x * (blockDim.x >> 5) + (threadIdx.x >> 5);
    const int lane = threadIdx.x & 31;
    const int b = g >> 6;
    const int p = g & 63;
    const float NEG_INF = __int_as_float(0xff800000);

    float v[4];
    int nidx[4];
#pragma unroll
    for (int q = 0; q < 4; q++) {
        int n = p + 64 * (lane + 32 * q);
        size_t off = (size_t)b * NN + n;
        v[q] = logits[off] + gumbel[off];
        nidx[q] = n;
    }

    for (int it = 0; it < KSEL; it++) {
        float bv = v[0]; int bn = nidx[0];
#pragma unroll
        for (int q = 1; q < 4; q++)
            if (v[q] > bv || (v[q] == bv && nidx[q] < bn)) { bv = v[q]; bn = nidx[q]; }
#pragma unroll
        for (int off = 16; off; off >>= 1) {
            float ov = __shfl_xor_sync(0xFFFFFFFFu, bv, off);
            int   on = __shfl_xor_sync(0xFFFFFFFFu, bn, off);
            if (ov > bv || (ov == bv && on < bn)) { bv = ov; bn = on; }
        }
        if (lane == 0)
            out_idx[(size_t)b * SEL_PER_B + p * KSEL + it] = (float)bn;
#pragma unroll
        for (int q = 0; q < 4; q++)
            if (nidx[q] == bn) v[q] = NEG_INF;
    }
}

// ============================================================
// K3: gather selected patch rows, 4 rows per warp with all loads
// issued before stores (MLP 8 per lane).
// ============================================================
__global__ __launch_bounds__(256)
void k_gather(const float* __restrict__ patches,
              const float* __restrict__ out_idx,
              float* __restrict__ out_sel)
{
    const int warp = blockIdx.x * 8 + (threadIdx.x >> 5);  // 0..8191
    const int lane = threadIdx.x & 31;
    const int j0 = warp * 4;                 // 4 rows per warp
    const int b = j0 >> 11;
    const int jb = j0 & 2047;

    int n[4];
#pragma unroll
    for (int r = 0; r < 4; r++)
        n[r] = (int)out_idx[(size_t)b * SEL_PER_B + jb + r];

    float4 v[8];
#pragma unroll
    for (int r = 0; r < 4; r++) {
        const float4* src = (const float4*)&patches[((size_t)b * NN + n[r]) * DD];
        v[2 * r]     = src[lane];
        v[2 * r + 1] = src[lane + 32];
    }
#pragma unroll
    for (int r = 0; r < 4; r++) {
        float4* dst = (float4*)&out_sel[((size_t)b * SEL_PER_B + jb + r) * DD];
        dst[lane]      = v[2 * r];
        dst[lane + 32] = v[2 * r + 1];
    }
}

// ============================================================
// launch
// ============================================================
extern "C" void kernel_launch(void* const* d_in, const int* in_sizes, int n_in,
                              void* d_out, int out_size)
{
    const float* patches  = (const float*)d_in[0];
    const float* features = (const float*)d_in[1];
    const float* W1       = (const float*)d_in[2];
    const float* b1       = (const float*)d_in[3];
    const float* W2       = (const float*)d_in[4];
    const float* b2       = (const float*)d_in[5];
    const float* gumbel   = (const float*)d_in[6];

    float* out      = (float*)d_out;
    float* out_sel  = out;                                 // [B, 2048, 256]
    float* out_idx  = out + (size_t)BB * SEL_PER_B * DD;   // [B, 2048]
    float* out_log  = out_idx + (size_t)BB * SEL_PER_B;    // [B, N]

    k_prepB<<<64, 256>>>(W1);
    k_logits_tc<<<ROWS / 128, 128>>>(features, b1, W2, b2, out_log);
    k_select<<<(BB * NP) / 8, 256>>>(out_log, gumbel, out_idx);
    k_gather<<<BB * SEL_PER_B / 32, 256>>>(patches, out_idx, out_sel);
}

// round 11
// speedup vs baseline: 1.3491x; 1.0277x over previous
#include <cuda_runtime.h>
#include <cuda_fp16.h>
#include <stdint.h>

// Problem constants
#define BB 16
#define NN 8192
#define DD 256
#define HH 128
#define NP 64
#define KSEL 32
#define ROWS (BB * NN)          // 131072
#define SEL_PER_B (NP * KSEL)   // 2048

#define LO_SCALE 2048.0f        // 2^11 (B residual plane scale)
#define LO_INV   (1.0f / 2048.0f)

// ---- fp16 pack helpers ----
__device__ __forceinline__ uint32_t pack_h2(float x, float y) {
    __half2 h = __floats2half2_rn(x, y);
    return *reinterpret_cast<uint32_t*>(&h);
}
__device__ __forceinline__ float2 unpack_h2(uint32_t u) {
    __half2 h = *reinterpret_cast<__half2*>(&u);
    return __half22float2(h);
}

__device__ __forceinline__ void mma_f16(float c[4],
                                        uint32_t a0, uint32_t a1, uint32_t a2, uint32_t a3,
                                        uint32_t b0, uint32_t b1) {
    asm volatile(
        "mma.sync.aligned.m16n8k16.row.col.f32.f16.f16.f32 "
        "{%0,%1,%2,%3}, {%4,%5,%6,%7}, {%8,%9}, {%0,%1,%2,%3};"
        : "+f"(c[0]), "+f"(c[1]), "+f"(c[2]), "+f"(c[3])
        : "r"(a0), "r"(a1), "r"(a2), "r"(a3), "r"(b0), "r"(b1));
}
__device__ __forceinline__ void mma_f16_z(float d[4],
                                          uint32_t a0, uint32_t a1, uint32_t a2, uint32_t a3,
                                          uint32_t b0, uint32_t b1,
                                          const float z[4]) {
    asm volatile(
        "mma.sync.aligned.m16n8k16.row.col.f32.f16.f16.f32 "
        "{%0,%1,%2,%3}, {%4,%5,%6,%7}, {%8,%9}, {%10,%11,%12,%13};"
        : "=f"(d[0]), "=f"(d[1]), "=f"(d[2]), "=f"(d[3])
        : "r"(a0), "r"(a1), "r"(a2), "r"(a3), "r"(b0), "r"(b1),
          "f"(z[0]), "f"(z[1]), "f"(z[2]), "f"(z[3]));
}

__device__ __forceinline__ uint32_t smem_u32(const void* p) {
    uint32_t a;
    asm("{ .reg .u64 t; cvta.to.shared.u64 t, %1; cvt.u32.u64 %0, t; }" : "=r"(a) : "l"(p));
    return a;
}
__device__ __forceinline__ void cp_async16(uint32_t dst, const void* src) {
    asm volatile("cp.async.cg.shared.global [%0], [%1], 16;" :: "r"(dst), "l"(src));
}
__device__ __forceinline__ void cp_async8(uint32_t dst, const void* src) {
    asm volatile("cp.async.ca.shared.global [%0], [%1], 8;" :: "r"(dst), "l"(src));
}
#define CP_COMMIT() asm volatile("cp.async.commit_group;")
#define CP_WAIT0()  asm volatile("cp.async.wait_group 0;")

// W1 planes, mma B-fragment layout: plane0 = fp16(w), plane1 = fp16((w-hi)*2^11)
__device__ uint2 g_Bf[16][16][2][32];

// ============================================================
// K0: build W1 fragment table
// ============================================================
__global__ void k_prepB(const float* __restrict__ W1)
{
    int idx  = blockIdx.x * 256 + threadIdx.x;
    int lane = idx & 31;
    int pl   = (idx >> 5) & 1;
    int nt   = (idx >> 6) & 15;
    int kt   = idx >> 10;

    int k0 = kt * 16 + (lane & 3) * 2;
    int n  = nt * 8 + (lane >> 2);

    uint32_t reg[2];
#pragma unroll
    for (int r = 0; r < 2; r++) {
        int k = k0 + r * 8;
        float v0 = W1[(size_t)k * HH + n];
        float v1 = W1[(size_t)(k + 1) * HH + n];
        uint32_t h = pack_h2(v0, v1);
        if (pl == 0) {
            reg[r] = h;
        } else {
            float2 f = unpack_h2(h);
            reg[r] = pack_h2((v0 - f.x) * LO_SCALE, (v1 - f.y) * LO_SCALE);
        }
    }
    g_Bf[kt][nt][pl][lane] = make_uint2(reg[0], reg[1]);
}

// ============================================================
// K1: logits via fp16 3-product split mma.sync, interleaved so
// pass-3 tmp chains never serialize (4-wide tmp window).
// CTA 128x128, 128 threads, 4 warps (2wm x 2wn), warp 64x64.
// ============================================================
#define ASTRIDE 18

__global__ __launch_bounds__(128, 2)
void k_logits_tc(const float* __restrict__ features,
                 const float* __restrict__ b1,
                 const float* __restrict__ W2,
                 const float* __restrict__ b2,
                 float* __restrict__ logits)
{
    __shared__ float sA[2][128][ASTRIDE];
    __shared__ uint2 sB[2][16][2][32];
    __shared__ float s_b1[HH], s_w2[HH];
    __shared__ float s_red[128][2];

    const int tid  = threadIdx.x;
    const int wid  = tid >> 5;
    const int lane = tid & 31;
    const int wm   = wid >> 1;
    const int wn   = wid & 1;
    const int g    = lane >> 2;
    const int tig  = lane & 3;
    const int row0 = blockIdx.x * 128;

    if (tid < HH) { s_b1[tid] = b1[tid]; s_w2[tid] = W2[tid]; }

    const float* Abase = features + (size_t)row0 * DD;

    auto prefetch = [&](int stage, int kt) {
        const int koff = kt * 16;
#pragma unroll
        for (int i = 0; i < 8; i++) {
            int cidx = tid + 128 * i;
            int r = cidx >> 3;
            int c = cidx & 7;
            cp_async8(smem_u32(&sA[stage][r][c * 2]),
                      Abase + (size_t)r * DD + koff + c * 2);
        }
        const char* src = (const char*)&g_Bf[kt][0][0][0];
        uint32_t dst = smem_u32(&sB[stage][0][0][0]);
#pragma unroll
        for (int i = 0; i < 4; i++) {
            int c = tid + 128 * i;
            cp_async16(dst + c * 16, src + c * 16);
        }
        CP_COMMIT();
    };

    prefetch(0, 0);

    float acc[4][8][4];
#pragma unroll
    for (int mt = 0; mt < 4; mt++)
#pragma unroll
        for (int nt = 0; nt < 8; nt++)
#pragma unroll
            for (int c = 0; c < 4; c++) acc[mt][nt][c] = 0.0f;

    float zc[4] = {0.0f, 0.0f, 0.0f, 0.0f};

    const int rg = wm * 64 + g;
    const int kcol = tig * 2;

    for (int kt = 0; kt < 16; kt++) {
        const int buf = kt & 1;
        CP_WAIT0();
        __syncthreads();
        if (kt < 15) prefetch(buf ^ 1, kt + 1);

        uint2 bh[8], bl[8];
#pragma unroll
        for (int nt = 0; nt < 8; nt++) {
            const int ntg = wn * 8 + nt;
            bh[nt] = sB[buf][ntg][0][lane];
            bl[nt] = sB[buf][ntg][1][lane];
        }

        uint32_t Ah[4][4], Al[4][4];
#pragma unroll
        for (int mt = 0; mt < 4; mt++) {
            const int r0 = rg + mt * 16;
            float2 v00 = *(const float2*)&sA[buf][r0][kcol];
            float2 v10 = *(const float2*)&sA[buf][r0 + 8][kcol];
            float2 v01 = *(const float2*)&sA[buf][r0][kcol + 8];
            float2 v11 = *(const float2*)&sA[buf][r0 + 8][kcol + 8];
            Ah[mt][0] = pack_h2(v00.x, v00.y);
            Ah[mt][1] = pack_h2(v10.x, v10.y);
            Ah[mt][2] = pack_h2(v01.x, v01.y);
            Ah[mt][3] = pack_h2(v11.x, v11.y);
            float2 f;
            f = unpack_h2(Ah[mt][0]); Al[mt][0] = pack_h2(v00.x - f.x, v00.y - f.y);
            f = unpack_h2(Ah[mt][1]); Al[mt][1] = pack_h2(v10.x - f.x, v10.y - f.y);
            f = unpack_h2(Ah[mt][2]); Al[mt][2] = pack_h2(v01.x - f.x, v01.y - f.y);
            f = unpack_h2(Ah[mt][3]); Al[mt][3] = pack_h2(v11.x - f.x, v11.y - f.y);
        }

        // Interleaved per-nt schedule:
        //   tmp[mt] = Ah*Bl (4 indep MMAs)
        //   acc    += Ah*Bh (4 indep MMAs; cover tmp latency)
        //   acc    += tmp * 2^-11 (16 FFMA; tmp ready)
        //   acc    += Al*Bh (4 indep MMAs)
#pragma unroll
        for (int nt = 0; nt < 8; nt++) {
            float tmp[4][4];
#pragma unroll
            for (int mt = 0; mt < 4; mt++)
                mma_f16_z(tmp[mt], Ah[mt][0], Ah[mt][1], Ah[mt][2], Ah[mt][3],
                          bl[nt].x, bl[nt].y, zc);
#pragma unroll
            for (int mt = 0; mt < 4; mt++)
                mma_f16(acc[mt][nt], Ah[mt][0], Ah[mt][1], Ah[mt][2], Ah[mt][3],
                        bh[nt].x, bh[nt].y);
#pragma unroll
            for (int mt = 0; mt < 4; mt++)
#pragma unroll
                for (int c = 0; c < 4; c++)
                    acc[mt][nt][c] = fmaf(tmp[mt][c], LO_INV, acc[mt][nt][c]);
#pragma unroll
            for (int mt = 0; mt < 4; mt++)
                mma_f16(acc[mt][nt], Al[mt][0], Al[mt][1], Al[mt][2], Al[mt][3],
                        bh[nt].x, bh[nt].y);
        }
    }

    // Epilogue: relu(acc + b1) * W2, reduce over hidden
    float rs[8];
#pragma unroll
    for (int i = 0; i < 8; i++) rs[i] = 0.0f;
#pragma unroll
    for (int nt = 0; nt < 8; nt++) {
        const int c = wn * 64 + nt * 8 + tig * 2;
        float bb0 = s_b1[c],     w0 = s_w2[c];
        float bb1 = s_b1[c + 1], w1 = s_w2[c + 1];
#pragma unroll
        for (int mt = 0; mt < 4; mt++) {
            float x0 = acc[mt][nt][0] + bb0; x0 = x0 > 0.0f ? x0 : 0.0f;
            float x1 = acc[mt][nt][1] + bb1; x1 = x1 > 0.0f ? x1 : 0.0f;
            float x2 = acc[mt][nt][2] + bb0; x2 = x2 > 0.0f ? x2 : 0.0f;
            float x3 = acc[mt][nt][3] + bb1; x3 = x3 > 0.0f ? x3 : 0.0f;
            rs[2 * mt + 0] += x0 * w0 + x1 * w1;
            rs[2 * mt + 1] += x2 * w0 + x3 * w1;
        }
    }
#pragma unroll
    for (int off = 1; off <= 2; off <<= 1)
#pragma unroll
        for (int i = 0; i < 8; i++)
            rs[i] += __shfl_xor_sync(0xFFFFFFFFu, rs[i], off);

    if (tig == 0) {
#pragma unroll
        for (int mt = 0; mt < 4; mt++) {
            s_red[wm * 64 + mt * 16 + g][wn]     = rs[2 * mt + 0];
            s_red[wm * 64 + mt * 16 + g + 8][wn] = rs[2 * mt + 1];
        }
    }
    __syncthreads();
    if (tid < 128)
        logits[(size_t)row0 + tid] = s_red[tid][0] + s_red[tid][1] + __ldg(b2);
}

// ============================================================
// K2: per (batch, parcel) top-32 of z = logits + gumbel.
// ============================================================
__global__ void k_select(const float* __restrict__ logits,
                         const float* __restrict__ gumbel,
                         float* __restrict__ out_idx)
{
    const int g = blockIdx.x * (blockDim.x >> 5) + (threadIdx.x >> 5);
    const int lane = threadIdx.x & 31;
    const int b = g >> 6;
    const int p = g & 63;
    const float NEG_INF = __int_as_float(0xff800000);

    float v[4];
    int nidx[4];
#pragma unroll
    for (int q = 0; q < 4; q++) {
        int n = p + 64 * (lane + 32 * q);
        size_t off = (size_t)b * NN + n;
        v[q] = logits[off] + gumbel[off];
        nidx[q] = n;
    }

    for (int it = 0; it < KSEL; it++) {
        float bv = v[0]; int bn = nidx[0];
#pragma unroll
        for (int q = 1; q < 4; q++)
            if (v[q] > bv || (v[q] == bv && nidx[q] < bn)) { bv = v[q]; bn = nidx[q]; }
#pragma unroll
        for (int off = 16; off; off >>= 1) {
            float ov = __shfl_xor_sync(0xFFFFFFFFu, bv, off);
            int   on = __shfl_xor_sync(0xFFFFFFFFu, bn, off);
            if (ov > bv || (ov == bv && on < bn)) { bv = ov; bn = on; }
        }
        if (lane == 0)
            out_idx[(size_t)b * SEL_PER_B + p * KSEL + it] = (float)bn;
#pragma unroll
        for (int q = 0; q < 4; q++)
            if (nidx[q] == bn) v[q] = NEG_INF;
    }
}

// ============================================================
// K3: gather selected patch rows (warp per row — round-8 form).
// ============================================================
__global__ __launch_bounds__(256)
void k_gather(const float* __restrict__ patches,
              const float* __restrict__ out_idx,
              float* __restrict__ out_sel)
{
    const int gw = blockIdx.x * 8 + (threadIdx.x >> 5);
    const int lane = threadIdx.x & 31;
    const int b = gw >> 11;
    const int j = gw & 2047;
    const int n = (int)out_idx[(size_t)b * SEL_PER_B + j];
    const float4* src = (const float4*)&patches[((size_t)b * NN + n) * DD];
    float4* dst = (float4*)&out_sel[((size_t)b * SEL_PER_B + j) * DD];
    dst[lane]      = src[lane];
    dst[lane + 32] = src[lane + 32];
}

// ============================================================
// launch
// ============================================================
extern "C" void kernel_launch(void* const* d_in, const int* in_sizes, int n_in,
                              void* d_out, int out_size)
{
    const float* patches  = (const float*)d_in[0];
    const float* features = (const float*)d_in[1];
    const float* W1       = (const float*)d_in[2];
    const float* b1       = (const float*)d_in[3];
    const float* W2       = (const float*)d_in[4];
    const float* b2       = (const float*)d_in[5];
    const float* gumbel   = (const float*)d_in[6];

    float* out      = (float*)d_out;
    float* out_sel  = out;                                 // [B, 2048, 256]
    float* out_idx  = out + (size_t)BB * SEL_PER_B * DD;   // [B, 2048]
    float* out_log  = out_idx + (size_t)BB * SEL_PER_B;    // [B, N]

    k_prepB<<<64, 256>>>(W1);
    k_logits_tc<<<ROWS / 128, 128>>>(features, b1, W2, b2, out_log);
    k_select<<<(BB * NP) / 8, 256>>>(out_log, gumbel, out_idx);
    k_gather<<<BB * SEL_PER_B / 8, 256>>>(patches, out_idx, out_sel);
}